// round 1
// baseline (speedup 1.0000x reference)
#include <cuda_runtime.h>
#include <math.h>

// ---------------- problem constants ----------------
#define Bq   8
#define Nn   1024
#define Cc   12
#define Ee   256
#define Hh   8
#define Dh   32
#define Ll   4
#define Tt   1025          // N + 1 (cls prepended)
#define XE   1024          // 4*E
#define NCc  5
#define EPSv 1e-5f
#define Mrows (Bq*Tt)      // 8200

// ---------------- scratch (device globals; no allocs) ----------------
__device__ float g_h [Bq*Tt*Ee];
__device__ float g_y [Bq*Tt*Ee];
__device__ float g_q [Bq*Tt*Ee];
__device__ float g_k [Bq*Tt*Ee];
__device__ float g_v [Bq*Tt*Ee];
__device__ float g_m [Bq*Tt*XE];
__device__ float g_p [Bq*Ee];
__device__ float g_S [(size_t)Bq*Hh*Tt*Tt];   // 269 MB attention scores

// ---------------- helpers ----------------
__device__ __forceinline__ float gelu_exact(float x) {
    return 0.5f * x * (1.0f + erff(x * 0.70710678118654752f));
}

__device__ __forceinline__ float blockReduceSum(float v, float* red) {
    int t = threadIdx.x;
    red[t] = v; __syncthreads();
    for (int s = blockDim.x >> 1; s > 0; s >>= 1) {
        if (t < s) red[t] += red[t + s];
        __syncthreads();
    }
    float r = red[0]; __syncthreads();
    return r;
}

__device__ __forceinline__ float blockReduceMax(float v, float* red) {
    int t = threadIdx.x;
    red[t] = v; __syncthreads();
    for (int s = blockDim.x >> 1; s > 0; s >>= 1) {
        if (t < s) red[t] = fmaxf(red[t], red[t + s]);
        __syncthreads();
    }
    float r = red[0]; __syncthreads();
    return r;
}

// ---------------- embedding: gelu(ln(x @ W_emb + b)) -> h[:,1:,:] ----------------
// grid = B*Nn blocks, 256 threads (one per output channel)
__global__ void embed_kernel(const float* __restrict__ x,
                             const float* __restrict__ W,  // [C,E]
                             const float* __restrict__ bias,
                             const float* __restrict__ g,
                             const float* __restrict__ be,
                             float* __restrict__ h) {
    int row = blockIdx.x;           // b*Nn + n
    int b = row / Nn, n = row % Nn;
    int e = threadIdx.x;
    __shared__ float xr[Cc];
    __shared__ float red[256];
    if (e < Cc) xr[e] = x[(size_t)row * Cc + e];
    __syncthreads();
    float acc = bias[e];
#pragma unroll
    for (int c = 0; c < Cc; ++c) acc += xr[c] * W[c * Ee + e];
    float mean = blockReduceSum(acc, red) * (1.0f / Ee);
    float d = acc - mean;
    float var = blockReduceSum(d * d, red) * (1.0f / Ee);
    float v = d * rsqrtf(var + EPSv) * g[e] + be[e];
    h[((size_t)b * Tt + (n + 1)) * Ee + e] = gelu_exact(v);
}

// cls row
__global__ void cls_kernel(const float* __restrict__ cls, float* __restrict__ h) {
    int b = blockIdx.x, e = threadIdx.x;
    h[(size_t)b * Tt * Ee + e] = cls[e];
}

// h += pos (broadcast over batch)
__global__ void add_pos_kernel(float* __restrict__ h, const float* __restrict__ pos) {
    size_t idx = (size_t)blockIdx.x * blockDim.x + threadIdx.x;
    if (idx >= (size_t)Bq * Tt * Ee) return;
    size_t te = idx % ((size_t)Tt * Ee);
    h[idx] += pos[te];
}

// layernorm per row of E
__global__ void ln_kernel(const float* __restrict__ h,
                          const float* __restrict__ g,
                          const float* __restrict__ bb,
                          float* __restrict__ y) {
    int row = blockIdx.x;
    int e = threadIdx.x;
    __shared__ float red[256];
    float v = h[(size_t)row * Ee + e];
    float mean = blockReduceSum(v, red) * (1.0f / Ee);
    float d = v - mean;
    float var = blockReduceSum(d * d, red) * (1.0f / Ee);
    y[(size_t)row * Ee + e] = d * rsqrtf(var + EPSv) * g[e] + bb[e];
}

// ---------------- tiled SGEMM: C = epi(A[M,K] @ B[K,N] + bias) (+res) ----------------
#define EPI_NONE 0
#define EPI_GELU 1
#define EPI_ADD  2
#define BM 64
#define BN 64
#define BK 16

template <int EPI>
__global__ __launch_bounds__(256) void sgemm_kernel(
    const float* __restrict__ A, const float* __restrict__ B,
    const float* __restrict__ bias, const float* __restrict__ res,
    float* __restrict__ C, int M, int N, int K) {
    __shared__ __align__(16) float As[BK][BM];
    __shared__ __align__(16) float Bs[BK][BN];

    int bm = blockIdx.y * BM;
    int bn = blockIdx.x * BN;
    int t = threadIdx.x;
    int tx = t & 15, ty = t >> 4;

    float acc[4][4];
#pragma unroll
    for (int i = 0; i < 4; ++i)
#pragma unroll
        for (int j = 0; j < 4; ++j) acc[i][j] = 0.0f;

    // A-load mapping: thread -> (row = t>>2, 4 ks at (t&3)*4)
    int ar = t >> 2, aks = (t & 3) * 4;
    // B-load mapping: thread -> (krow = t>>4, 4 ns at (t&15)*4)
    int bkr = t >> 4, bnc = (t & 15) * 4;

    for (int k0 = 0; k0 < K; k0 += BK) {
        // load A tile (zero-pad rows >= M); K % 16 == 0 guaranteed here
        float4 av = make_float4(0.f, 0.f, 0.f, 0.f);
        if (bm + ar < M)
            av = *reinterpret_cast<const float4*>(&A[(size_t)(bm + ar) * K + k0 + aks]);
        As[aks + 0][ar] = av.x;
        As[aks + 1][ar] = av.y;
        As[aks + 2][ar] = av.z;
        As[aks + 3][ar] = av.w;
        // load B tile (N % 64 == 0, K % 16 == 0)
        float4 bv = *reinterpret_cast<const float4*>(&B[(size_t)(k0 + bkr) * N + bn + bnc]);
        *reinterpret_cast<float4*>(&Bs[bkr][bnc]) = bv;
        __syncthreads();

#pragma unroll
        for (int kk = 0; kk < BK; ++kk) {
            float4 am = *reinterpret_cast<const float4*>(&As[kk][ty * 4]);
            float4 bw = *reinterpret_cast<const float4*>(&Bs[kk][tx * 4]);
            float amv[4] = {am.x, am.y, am.z, am.w};
            float bnv[4] = {bw.x, bw.y, bw.z, bw.w};
#pragma unroll
            for (int i = 0; i < 4; ++i)
#pragma unroll
                for (int j = 0; j < 4; ++j) acc[i][j] = fmaf(amv[i], bnv[j], acc[i][j]);
        }
        __syncthreads();
    }

#pragma unroll
    for (int i = 0; i < 4; ++i) {
        int m = bm + ty * 4 + i;
        if (m >= M) continue;
#pragma unroll
        for (int j = 0; j < 4; ++j) {
            int n = bn + tx * 4 + j;
            float val = acc[i][j] + bias[n];
            if (EPI == EPI_GELU) val = gelu_exact(val);
            if (EPI == EPI_ADD)  val += res[(size_t)m * N + n];
            C[(size_t)m * N + n] = val;
        }
    }
}

// ---------------- attention scores: S[bh,i,j] = sum_d q[b,i,h,d]*k[b,j,h,d] ----------------
// grid (33, 33, B*H), 256 threads, 32x32 output tile, K=32 resident
__global__ __launch_bounds__(256) void attn_scores_kernel(
    const float* __restrict__ q, const float* __restrict__ k, float* __restrict__ S) {
    int bh = blockIdx.z;
    int b = bh / Hh, h = bh % Hh;
    int i0 = blockIdx.y * 32, j0 = blockIdx.x * 32;
    __shared__ __align__(16) float Qs[32][33];
    __shared__ __align__(16) float Ks[32][33];
    int t = threadIdx.x;
    int r = t >> 3, c4 = (t & 7) * 4;

    const float* qb = q + (size_t)b * Tt * Ee + h * Dh;
    const float* kb = k + (size_t)b * Tt * Ee + h * Dh;

    float4 qv = make_float4(0.f, 0.f, 0.f, 0.f);
    float4 kv = make_float4(0.f, 0.f, 0.f, 0.f);
    if (i0 + r < Tt) qv = *reinterpret_cast<const float4*>(&qb[(size_t)(i0 + r) * Ee + c4]);
    if (j0 + r < Tt) kv = *reinterpret_cast<const float4*>(&kb[(size_t)(j0 + r) * Ee + c4]);
    Qs[r][c4 + 0] = qv.x; Qs[r][c4 + 1] = qv.y; Qs[r][c4 + 2] = qv.z; Qs[r][c4 + 3] = qv.w;
    Ks[r][c4 + 0] = kv.x; Ks[r][c4 + 1] = kv.y; Ks[r][c4 + 2] = kv.z; Ks[r][c4 + 3] = kv.w;
    __syncthreads();

    int tx = t & 15, ty = t >> 4;
    float acc[2][2] = {{0.f, 0.f}, {0.f, 0.f}};
#pragma unroll
    for (int d = 0; d < 32; ++d) {
        float q0 = Qs[ty * 2 + 0][d], q1 = Qs[ty * 2 + 1][d];
        float k0v = Ks[tx * 2 + 0][d], k1v = Ks[tx * 2 + 1][d];
        acc[0][0] = fmaf(q0, k0v, acc[0][0]);
        acc[0][1] = fmaf(q0, k1v, acc[0][1]);
        acc[1][0] = fmaf(q1, k0v, acc[1][0]);
        acc[1][1] = fmaf(q1, k1v, acc[1][1]);
    }
    float* Sb = S + (size_t)bh * Tt * Tt;
#pragma unroll
    for (int ii = 0; ii < 2; ++ii) {
        int i = i0 + ty * 2 + ii;
        if (i >= Tt) continue;
#pragma unroll
        for (int jj = 0; jj < 2; ++jj) {
            int j = j0 + tx * 2 + jj;
            if (j < Tt) Sb[(size_t)i * Tt + j] = acc[ii][jj];
        }
    }
}

// ---------------- softmax over last dim, then scale by 1/16 (scale AFTER softmax) ----
__global__ void softmax_kernel(float* __restrict__ S) {
    size_t row = blockIdx.x;
    float* p = S + row * (size_t)Tt;
    int t = threadIdx.x;
    __shared__ float red[256];
    float mx = -3.0e38f;
    for (int j = t; j < Tt; j += 256) mx = fmaxf(mx, p[j]);
    mx = blockReduceMax(mx, red);
    float sum = 0.f;
    for (int j = t; j < Tt; j += 256) {
        float e = expf(p[j] - mx);
        p[j] = e;
        sum += e;
    }
    sum = blockReduceSum(sum, red);
    float inv = 1.0f / (sum * 16.0f);   // sqrt(E)=16, applied post-softmax per reference
    for (int j = t; j < Tt; j += 256) p[j] *= inv;
}

// ---------------- attention output: O[b,i,h,d] = sum_j P[bh,i,j] * v[b,j,h,d] ----------
// grid (33, B*H), 256 threads, output tile 32(i) x 32(d)
__global__ __launch_bounds__(256) void attn_out_kernel(
    const float* __restrict__ S, const float* __restrict__ v, float* __restrict__ o) {
    int bh = blockIdx.y;
    int b = bh / Hh, h = bh % Hh;
    int i0 = blockIdx.x * 32;
    __shared__ __align__(16) float Ps[32][33];
    __shared__ __align__(16) float Vs[32][33];
    int t = threadIdx.x;
    int r = t >> 3, c4 = (t & 7) * 4;
    int tx = t & 15, ty = t >> 4;

    const float* Sb = S + (size_t)bh * Tt * Tt;
    const float* vb = v + (size_t)b * Tt * Ee + h * Dh;

    float acc[2][2] = {{0.f, 0.f}, {0.f, 0.f}};
    for (int j0 = 0; j0 < Tt; j0 += 32) {
        // P tile (scalar loads: row stride 1025 breaks float4 alignment)
#pragma unroll
        for (int u = 0; u < 4; ++u) {
            int j = j0 + c4 + u;
            Ps[r][c4 + u] = (i0 + r < Tt && j < Tt) ? Sb[(size_t)(i0 + r) * Tt + j] : 0.f;
        }
        // V tile
        float4 vv = make_float4(0.f, 0.f, 0.f, 0.f);
        if (j0 + r < Tt) vv = *reinterpret_cast<const float4*>(&vb[(size_t)(j0 + r) * Ee + c4]);
        Vs[r][c4 + 0] = vv.x; Vs[r][c4 + 1] = vv.y; Vs[r][c4 + 2] = vv.z; Vs[r][c4 + 3] = vv.w;
        __syncthreads();

#pragma unroll
        for (int kk = 0; kk < 32; ++kk) {
            float p0 = Ps[ty * 2 + 0][kk], p1 = Ps[ty * 2 + 1][kk];
            float v0 = Vs[kk][tx * 2 + 0], v1 = Vs[kk][tx * 2 + 1];
            acc[0][0] = fmaf(p0, v0, acc[0][0]);
            acc[0][1] = fmaf(p0, v1, acc[0][1]);
            acc[1][0] = fmaf(p1, v0, acc[1][0]);
            acc[1][1] = fmaf(p1, v1, acc[1][1]);
        }
        __syncthreads();
    }
#pragma unroll
    for (int ii = 0; ii < 2; ++ii) {
        int i = i0 + ty * 2 + ii;
        if (i >= Tt) continue;
#pragma unroll
        for (int jj = 0; jj < 2; ++jj) {
            int d = tx * 2 + jj;
            o[((size_t)b * Tt + i) * Ee + h * Dh + d] = acc[ii][jj];
        }
    }
}

// ---------------- mean pool over tokens ----------------
__global__ void pool_kernel(const float* __restrict__ h, float* __restrict__ p) {
    int b = blockIdx.x, e = threadIdx.x;
    float sum = 0.f;
    for (int t = 0; t < Tt; ++t) sum += h[((size_t)b * Tt + t) * Ee + e];
    p[b * Ee + e] = sum * (1.0f / Tt);
}

// ---------------- classifier: ln(p@Wc1+bc1) @ Wc2 + bc2 ----------------
__global__ void classifier_kernel(const float* __restrict__ p,
                                  const float* __restrict__ Wc1, const float* __restrict__ bc1,
                                  const float* __restrict__ lg, const float* __restrict__ lb,
                                  const float* __restrict__ Wc2, const float* __restrict__ bc2,
                                  float* __restrict__ out) {
    int b = blockIdx.x, e = threadIdx.x;
    __shared__ float pr[Ee];
    __shared__ float u[Ee];
    __shared__ float red[256];
    pr[e] = p[b * Ee + e];
    __syncthreads();
    float acc = bc1[e];
    for (int kk = 0; kk < Ee; ++kk) acc = fmaf(pr[kk], Wc1[kk * Ee + e], acc);
    float mean = blockReduceSum(acc, red) * (1.0f / Ee);
    float d = acc - mean;
    float var = blockReduceSum(d * d, red) * (1.0f / Ee);
    u[e] = d * rsqrtf(var + EPSv) * lg[e] + lb[e];
    __syncthreads();
    if (e < NCc) {
        float o = bc2[e];
        for (int kk = 0; kk < Ee; ++kk) o = fmaf(u[kk], Wc2[kk * NCc + e], o);
        out[b * NCc + e] = o;
    }
}

// ---------------- launch ----------------
extern "C" void kernel_launch(void* const* d_in, const int* in_sizes, int n_in,
                              void* d_out, int out_size) {
    const float* x        = (const float*)d_in[0];
    const float* W_emb    = (const float*)d_in[1];
    const float* b_emb    = (const float*)d_in[2];
    const float* g_emb    = (const float*)d_in[3];
    const float* be_emb   = (const float*)d_in[4];
    const float* cls_tok  = (const float*)d_in[5];
    const float* pos      = (const float*)d_in[6];
    const float* ln1_g    = (const float*)d_in[7];
    const float* ln1_b    = (const float*)d_in[8];
    const float* Wq       = (const float*)d_in[9];
    const float* bq       = (const float*)d_in[10];
    const float* Wk       = (const float*)d_in[11];
    const float* bk       = (const float*)d_in[12];
    const float* Wv       = (const float*)d_in[13];
    const float* bv       = (const float*)d_in[14];
    const float* Wo       = (const float*)d_in[15];
    const float* bo       = (const float*)d_in[16];
    const float* ln2_g    = (const float*)d_in[17];
    const float* ln2_b    = (const float*)d_in[18];
    const float* W1       = (const float*)d_in[19];
    const float* b1       = (const float*)d_in[20];
    const float* W2       = (const float*)d_in[21];
    const float* b2       = (const float*)d_in[22];
    const float* Wc1      = (const float*)d_in[23];
    const float* bc1      = (const float*)d_in[24];
    const float* lnc_g    = (const float*)d_in[25];
    const float* lnc_b    = (const float*)d_in[26];
    const float* Wc2      = (const float*)d_in[27];
    const float* bc2      = (const float*)d_in[28];

    float *h, *y, *q, *k, *v, *mlp, *p, *S;
    cudaGetSymbolAddress((void**)&h,   g_h);
    cudaGetSymbolAddress((void**)&y,   g_y);
    cudaGetSymbolAddress((void**)&q,   g_q);
    cudaGetSymbolAddress((void**)&k,   g_k);
    cudaGetSymbolAddress((void**)&v,   g_v);
    cudaGetSymbolAddress((void**)&mlp, g_m);
    cudaGetSymbolAddress((void**)&p,   g_p);
    cudaGetSymbolAddress((void**)&S,   g_S);

    embed_kernel<<<Bq * Nn, 256>>>(x, W_emb, b_emb, g_emb, be_emb, h);
    cls_kernel<<<Bq, 256>>>(cls_tok, h);

    const int M = Mrows;                          // 8200
    dim3 gemm256(Ee / BN, (M + BM - 1) / BM);     // (4, 129)
    dim3 gemm1024(XE / BN, (M + BM - 1) / BM);    // (16, 129)
    int totalHE = Bq * Tt * Ee;

    for (int l = 0; l < Ll; ++l) {
        add_pos_kernel<<<(totalHE + 255) / 256, 256>>>(h, pos);
        ln_kernel<<<M, 256>>>(h, ln1_g + l * Ee, ln1_b + l * Ee, y);

        sgemm_kernel<EPI_NONE><<<gemm256, 256>>>(y, Wq + (size_t)l * Ee * Ee, bq + l * Ee, nullptr, q, M, Ee, Ee);
        sgemm_kernel<EPI_NONE><<<gemm256, 256>>>(y, Wk + (size_t)l * Ee * Ee, bk + l * Ee, nullptr, k, M, Ee, Ee);
        sgemm_kernel<EPI_NONE><<<gemm256, 256>>>(y, Wv + (size_t)l * Ee * Ee, bv + l * Ee, nullptr, v, M, Ee, Ee);

        dim3 sgrid((Tt + 31) / 32, (Tt + 31) / 32, Bq * Hh);
        attn_scores_kernel<<<sgrid, 256>>>(q, k, S);
        softmax_kernel<<<Bq * Hh * Tt, 256>>>(S);
        dim3 ogrid((Tt + 31) / 32, Bq * Hh);
        attn_out_kernel<<<ogrid, 256>>>(S, v, y);   // y reused as attn output

        sgemm_kernel<EPI_ADD><<<gemm256, 256>>>(y, Wo + (size_t)l * Ee * Ee, bo + l * Ee, h, h, M, Ee, Ee);

        ln_kernel<<<M, 256>>>(h, ln2_g + l * Ee, ln2_b + l * Ee, y);
        sgemm_kernel<EPI_GELU><<<gemm1024, 256>>>(y, W1 + (size_t)l * Ee * XE, b1 + l * XE, nullptr, mlp, M, XE, Ee);
        sgemm_kernel<EPI_ADD><<<gemm256, 256>>>(mlp, W2 + (size_t)l * XE * Ee, b2 + l * Ee, h, h, M, Ee, XE);
    }

    pool_kernel<<<Bq, 256>>>(h, p);
    classifier_kernel<<<Bq, 256>>>(p, Wc1, bc1, lnc_g, lnc_b, Wc2, bc2, (float*)d_out);
}

// round 2
// speedup vs baseline: 1.3349x; 1.3349x over previous
#include <cuda_runtime.h>
#include <math.h>

// ---------------- problem constants ----------------
#define Bq   8
#define Nn   1024
#define Cc   12
#define Ee   256
#define Hh   8
#define Dh   32
#define Ll   4
#define Tt   1025          // N + 1 (cls prepended)
#define XE   1024          // 4*E
#define NCc  5
#define EPSv 1e-5f
#define Mrows (Bq*Tt)      // 8200

// ---------------- scratch (device globals; no allocs) ----------------
__device__ float g_h [Bq*Tt*Ee];
__device__ float g_y [Bq*Tt*Ee];
__device__ float g_q [Bq*Tt*Ee];
__device__ float g_k [Bq*Tt*Ee];
__device__ float g_v [Bq*Tt*Ee];
__device__ float g_m [Bq*Tt*XE];
__device__ float g_pp[4*Bq*Ee];       // pooling partials

// ---------------- helpers ----------------
__device__ __forceinline__ float gelu_exact(float x) {
    return 0.5f * x * (1.0f + erff(x * 0.70710678118654752f));
}

// block-wide sum over 256 threads, warp-shuffle based
__device__ __forceinline__ float blockSum256(float v, float* red8) {
    int t = threadIdx.x;
#pragma unroll
    for (int off = 16; off > 0; off >>= 1)
        v += __shfl_xor_sync(0xffffffffu, v, off);
    if ((t & 31) == 0) red8[t >> 5] = v;
    __syncthreads();
    float r = red8[0];
#pragma unroll
    for (int w = 1; w < 8; ++w) r += red8[w];
    __syncthreads();
    return r;
}

// ---------------- embedding: gelu(ln(x @ W_emb + b)) -> h[:,1:,:] ----------------
__global__ void embed_kernel(const float* __restrict__ x,
                             const float* __restrict__ W,  // [C,E]
                             const float* __restrict__ bias,
                             const float* __restrict__ g,
                             const float* __restrict__ be,
                             float* __restrict__ h) {
    int row = blockIdx.x;           // b*Nn + n
    int b = row / Nn, n = row % Nn;
    int e = threadIdx.x;
    __shared__ float xr[Cc];
    __shared__ float red8[8];
    if (e < Cc) xr[e] = x[(size_t)row * Cc + e];
    __syncthreads();
    float acc = bias[e];
#pragma unroll
    for (int c = 0; c < Cc; ++c) acc += xr[c] * W[c * Ee + e];
    float mean = blockSum256(acc, red8) * (1.0f / Ee);
    float d = acc - mean;
    float var = blockSum256(d * d, red8) * (1.0f / Ee);
    float v = d * rsqrtf(var + EPSv) * g[e] + be[e];
    h[((size_t)b * Tt + (n + 1)) * Ee + e] = gelu_exact(v);
}

// cls row
__global__ void cls_kernel(const float* __restrict__ cls, float* __restrict__ h) {
    int b = blockIdx.x, e = threadIdx.x;
    h[(size_t)b * Tt * Ee + e] = cls[e];
}

// fused: h += pos (persistent) then y = LN(h)
__global__ void addpos_ln_kernel(float* __restrict__ h,
                                 const float* __restrict__ pos,
                                 const float* __restrict__ g,
                                 const float* __restrict__ bb,
                                 float* __restrict__ y) {
    int row = blockIdx.x;          // b*Tt + t
    int tok = row % Tt;
    int e = threadIdx.x;
    __shared__ float red8[8];
    float v = h[(size_t)row * Ee + e] + pos[(size_t)tok * Ee + e];
    h[(size_t)row * Ee + e] = v;
    float mean = blockSum256(v, red8) * (1.0f / Ee);
    float d = v - mean;
    float var = blockSum256(d * d, red8) * (1.0f / Ee);
    y[(size_t)row * Ee + e] = d * rsqrtf(var + EPSv) * g[e] + bb[e];
}

// plain LN
__global__ void ln_kernel(const float* __restrict__ h,
                          const float* __restrict__ g,
                          const float* __restrict__ bb,
                          float* __restrict__ y) {
    int row = blockIdx.x;
    int e = threadIdx.x;
    __shared__ float red8[8];
    float v = h[(size_t)row * Ee + e];
    float mean = blockSum256(v, red8) * (1.0f / Ee);
    float d = v - mean;
    float var = blockSum256(d * d, red8) * (1.0f / Ee);
    y[(size_t)row * Ee + e] = d * rsqrtf(var + EPSv) * g[e] + bb[e];
}

// ---------------- SGEMM v2: 128x64x16 tile, 8x4 microtile, double-buffered ----------
#define EPI_NONE 0
#define EPI_GELU 1
#define EPI_ADD  2
#define GBM 128
#define GBN 64
#define GBK 16

template <int EPI>
__global__ __launch_bounds__(256) void gemm2_kernel(
    const float* __restrict__ A, const float* __restrict__ B,
    const float* __restrict__ bias, const float* __restrict__ res,
    float* __restrict__ C, int M, int N, int K) {
    __shared__ __align__(16) float As[2][GBK][GBM + 4];  // [k][m], pad 132
    __shared__ __align__(16) float Bs[2][GBK][GBN + 4];  // pad 68

    int t = threadIdx.x;
    int tx = t & 15, ty = t >> 4;
    int bm = blockIdx.y * GBM, bn = blockIdx.x * GBN;

    // A load mapping: row = t>>1 (0..127), k-offset = (t&1)*8  (two float4)
    int arow = t >> 1, ak = (t & 1) * 8;
    bool arow_ok = (bm + arow) < M;
    const float* Aptr = A + (size_t)(bm + arow) * K + ak;
    // B load mapping: k-row = ty, col4 = tx*4
    const float* Bptr = B + (size_t)ty * N + bn + tx * 4;

    float4 a0, a1, b0;
    // prefetch tile 0
    a0 = make_float4(0.f, 0.f, 0.f, 0.f);
    a1 = a0;
    if (arow_ok) {
        a0 = *reinterpret_cast<const float4*>(Aptr);
        a1 = *reinterpret_cast<const float4*>(Aptr + 4);
    }
    b0 = *reinterpret_cast<const float4*>(Bptr);
    // store tile 0
    As[0][ak + 0][arow] = a0.x; As[0][ak + 1][arow] = a0.y;
    As[0][ak + 2][arow] = a0.z; As[0][ak + 3][arow] = a0.w;
    As[0][ak + 4][arow] = a1.x; As[0][ak + 5][arow] = a1.y;
    As[0][ak + 6][arow] = a1.z; As[0][ak + 7][arow] = a1.w;
    *reinterpret_cast<float4*>(&Bs[0][ty][tx * 4]) = b0;
    __syncthreads();

    float acc[8][4];
#pragma unroll
    for (int i = 0; i < 8; ++i)
#pragma unroll
        for (int j = 0; j < 4; ++j) acc[i][j] = 0.f;

    int nk = K / GBK;
    int buf = 0;
    for (int kt = 0; kt < nk; ++kt) {
        // prefetch next tile into regs
        if (kt + 1 < nk) {
            const float* Ap = Aptr + (size_t)(kt + 1) * GBK;
            a0 = make_float4(0.f, 0.f, 0.f, 0.f);
            a1 = a0;
            if (arow_ok) {
                a0 = *reinterpret_cast<const float4*>(Ap);
                a1 = *reinterpret_cast<const float4*>(Ap + 4);
            }
            b0 = *reinterpret_cast<const float4*>(Bptr + (size_t)(kt + 1) * GBK * N);
        }
        // compute current
#pragma unroll
        for (int kk = 0; kk < GBK; ++kk) {
            float4 af0 = *reinterpret_cast<const float4*>(&As[buf][kk][ty * 8]);
            float4 af1 = *reinterpret_cast<const float4*>(&As[buf][kk][ty * 8 + 4]);
            float4 bf  = *reinterpret_cast<const float4*>(&Bs[buf][kk][tx * 4]);
            float av[8] = {af0.x, af0.y, af0.z, af0.w, af1.x, af1.y, af1.z, af1.w};
            float bvv[4] = {bf.x, bf.y, bf.z, bf.w};
#pragma unroll
            for (int i = 0; i < 8; ++i)
#pragma unroll
                for (int j = 0; j < 4; ++j) acc[i][j] = fmaf(av[i], bvv[j], acc[i][j]);
        }
        // store next tile
        if (kt + 1 < nk) {
            int nb = buf ^ 1;
            As[nb][ak + 0][arow] = a0.x; As[nb][ak + 1][arow] = a0.y;
            As[nb][ak + 2][arow] = a0.z; As[nb][ak + 3][arow] = a0.w;
            As[nb][ak + 4][arow] = a1.x; As[nb][ak + 5][arow] = a1.y;
            As[nb][ak + 6][arow] = a1.z; As[nb][ak + 7][arow] = a1.w;
            *reinterpret_cast<float4*>(&Bs[nb][ty][tx * 4]) = b0;
        }
        __syncthreads();
        buf ^= 1;
    }

    // epilogue
    float4 bias4 = *reinterpret_cast<const float4*>(&bias[bn + tx * 4]);
#pragma unroll
    for (int i = 0; i < 8; ++i) {
        int m = bm + ty * 8 + i;
        if (m >= M) continue;
        float4 out;
        out.x = acc[i][0] + bias4.x;
        out.y = acc[i][1] + bias4.y;
        out.z = acc[i][2] + bias4.z;
        out.w = acc[i][3] + bias4.w;
        if (EPI == EPI_GELU) {
            out.x = gelu_exact(out.x); out.y = gelu_exact(out.y);
            out.z = gelu_exact(out.z); out.w = gelu_exact(out.w);
        }
        if (EPI == EPI_ADD) {
            float4 rv = *reinterpret_cast<const float4*>(&res[(size_t)m * N + bn + tx * 4]);
            out.x += rv.x; out.y += rv.y; out.z += rv.z; out.w += rv.w;
        }
        *reinterpret_cast<float4*>(&C[(size_t)m * N + bn + tx * 4]) = out;
    }
}

// ---------------- fused flash attention (fp32, online softmax) ----------------
// grid (ceil(Tt/32), B*H), 256 threads.
// thread (r = t>>3, g = t&7): row i0+r, j-cols g*4..g*4+3, d-cols g*4..g*4+3
__global__ __launch_bounds__(256) void flash_attn_kernel(
    const float* __restrict__ q, const float* __restrict__ k,
    const float* __restrict__ v, float* __restrict__ o) {
    int bh = blockIdx.y;
    int b = bh >> 3, h = bh & 7;
    int i0 = blockIdx.x * 32;
    int t = threadIdx.x;
    int r = t >> 3, g = t & 7;

    __shared__ __align__(16) float Qs [32][36];
    __shared__ __align__(16) float Kst[32][36];   // [d][j]
    __shared__ __align__(16) float Vs [32][36];   // [j][d]
    __shared__ __align__(16) float Ps [32][36];   // [i][j]

    const float* qb = q + (size_t)b * Tt * Ee + h * Dh;
    const float* kb = k + (size_t)b * Tt * Ee + h * Dh;
    const float* vb = v + (size_t)b * Tt * Ee + h * Dh;

    // load Q tile -> smem -> regs
    {
        float4 qv = make_float4(0.f, 0.f, 0.f, 0.f);
        if (i0 + r < Tt) qv = *reinterpret_cast<const float4*>(&qb[(size_t)(i0 + r) * Ee + g * 4]);
        *reinterpret_cast<float4*>(&Qs[r][g * 4]) = qv;
    }
    __syncthreads();
    float qreg[32];
#pragma unroll
    for (int dd = 0; dd < 8; ++dd) {
        float4 qv = *reinterpret_cast<const float4*>(&Qs[r][dd * 4]);
        qreg[dd * 4 + 0] = qv.x; qreg[dd * 4 + 1] = qv.y;
        qreg[dd * 4 + 2] = qv.z; qreg[dd * 4 + 3] = qv.w;
    }

    float m = -1e30f, l = 0.f;
    float O0 = 0.f, O1 = 0.f, O2 = 0.f, O3 = 0.f;

    for (int j0 = 0; j0 < Tt; j0 += 32) {
        // global loads first (overlap with barrier wait)
        float4 kv = make_float4(0.f, 0.f, 0.f, 0.f);
        float4 vv = kv;
        if (j0 + r < Tt) {
            kv = *reinterpret_cast<const float4*>(&kb[(size_t)(j0 + r) * Ee + g * 4]);
            vv = *reinterpret_cast<const float4*>(&vb[(size_t)(j0 + r) * Ee + g * 4]);
        }
        __syncthreads();   // previous iteration's Kst/Vs reads complete
        Kst[g * 4 + 0][r] = kv.x; Kst[g * 4 + 1][r] = kv.y;
        Kst[g * 4 + 2][r] = kv.z; Kst[g * 4 + 3][r] = kv.w;
        *reinterpret_cast<float4*>(&Vs[r][g * 4]) = vv;
        __syncthreads();

        // S tile: s[u] = q(row) . K(j0+g*4+u)
        float s0 = 0.f, s1 = 0.f, s2 = 0.f, s3 = 0.f;
#pragma unroll
        for (int d = 0; d < 32; ++d) {
            float4 kf = *reinterpret_cast<const float4*>(&Kst[d][g * 4]);
            float qd = qreg[d];
            s0 = fmaf(qd, kf.x, s0);
            s1 = fmaf(qd, kf.y, s1);
            s2 = fmaf(qd, kf.z, s2);
            s3 = fmaf(qd, kf.w, s3);
        }
        // mask padded j
        if (j0 + 32 > Tt) {
            int jb = j0 + g * 4;
            if (jb + 0 >= Tt) s0 = -1e30f;
            if (jb + 1 >= Tt) s1 = -1e30f;
            if (jb + 2 >= Tt) s2 = -1e30f;
            if (jb + 3 >= Tt) s3 = -1e30f;
        }
        // row max across 8 lanes
        float mt = fmaxf(fmaxf(s0, s1), fmaxf(s2, s3));
        mt = fmaxf(mt, __shfl_xor_sync(0xffffffffu, mt, 1));
        mt = fmaxf(mt, __shfl_xor_sync(0xffffffffu, mt, 2));
        mt = fmaxf(mt, __shfl_xor_sync(0xffffffffu, mt, 4));
        float mnew = fmaxf(m, mt);
        float corr = __expf(m - mnew);
        m = mnew;
        float p0 = __expf(s0 - mnew);
        float p1 = __expf(s1 - mnew);
        float p2 = __expf(s2 - mnew);
        float p3 = __expf(s3 - mnew);
        float ps = p0 + p1 + p2 + p3;
        ps += __shfl_xor_sync(0xffffffffu, ps, 1);
        ps += __shfl_xor_sync(0xffffffffu, ps, 2);
        ps += __shfl_xor_sync(0xffffffffu, ps, 4);
        l = l * corr + ps;
        O0 *= corr; O1 *= corr; O2 *= corr; O3 *= corr;

        float4 pv4 = make_float4(p0, p1, p2, p3);
        *reinterpret_cast<float4*>(&Ps[r][g * 4]) = pv4;
        __syncwarp();

        // O accumulate: O[d] += sum_j P[row][j] * V[j][d]
#pragma unroll
        for (int j = 0; j < 32; ++j) {
            float pj = Ps[r][j];
            float4 vf = *reinterpret_cast<const float4*>(&Vs[j][g * 4]);
            O0 = fmaf(pj, vf.x, O0);
            O1 = fmaf(pj, vf.y, O1);
            O2 = fmaf(pj, vf.z, O2);
            O3 = fmaf(pj, vf.w, O3);
        }
        __syncwarp();
    }

    float inv = 1.0f / (l * 16.0f);   // sqrt(E)=16 applied AFTER softmax (per reference)
    if (i0 + r < Tt) {
        float4 ov = make_float4(O0 * inv, O1 * inv, O2 * inv, O3 * inv);
        *reinterpret_cast<float4*>(
            &o[((size_t)b * Tt + (i0 + r)) * Ee + h * Dh + g * 4]) = ov;
    }
}

// ---------------- mean pool (partial over token chunks) ----------------
// grid (4, B): chunk c sums tokens t ≡ c (mod 4)
__global__ void pool_partial_kernel(const float* __restrict__ h, float* __restrict__ pp) {
    int c = blockIdx.x, b = blockIdx.y, e = threadIdx.x;
    float sum = 0.f;
    for (int t = c; t < Tt; t += 4)
        sum += h[((size_t)b * Tt + t) * Ee + e];
    pp[((size_t)c * Bq + b) * Ee + e] = sum;
}

// ---------------- classifier: ln(p@Wc1+bc1) @ Wc2 + bc2 ----------------
__global__ void classifier_kernel(const float* __restrict__ pp,
                                  const float* __restrict__ Wc1, const float* __restrict__ bc1,
                                  const float* __restrict__ lg, const float* __restrict__ lb,
                                  const float* __restrict__ Wc2, const float* __restrict__ bc2,
                                  float* __restrict__ out) {
    int b = blockIdx.x, e = threadIdx.x;
    __shared__ float pr[Ee];
    __shared__ float u[Ee];
    __shared__ float red8[8];
    float s = 0.f;
#pragma unroll
    for (int c = 0; c < 4; ++c) s += pp[((size_t)c * Bq + b) * Ee + e];
    pr[e] = s * (1.0f / Tt);
    __syncthreads();
    float acc = bc1[e];
    for (int kk = 0; kk < Ee; ++kk) acc = fmaf(pr[kk], Wc1[kk * Ee + e], acc);
    float mean = blockSum256(acc, red8) * (1.0f / Ee);
    float d = acc - mean;
    float var = blockSum256(d * d, red8) * (1.0f / Ee);
    u[e] = d * rsqrtf(var + EPSv) * lg[e] + lb[e];
    __syncthreads();
    if (e < NCc) {
        float o = bc2[e];
        for (int kk = 0; kk < Ee; ++kk) o = fmaf(u[kk], Wc2[kk * NCc + e], o);
        out[b * NCc + e] = o;
    }
}

// ---------------- launch ----------------
extern "C" void kernel_launch(void* const* d_in, const int* in_sizes, int n_in,
                              void* d_out, int out_size) {
    const float* x        = (const float*)d_in[0];
    const float* W_emb    = (const float*)d_in[1];
    const float* b_emb    = (const float*)d_in[2];
    const float* g_emb    = (const float*)d_in[3];
    const float* be_emb   = (const float*)d_in[4];
    const float* cls_tok  = (const float*)d_in[5];
    const float* pos      = (const float*)d_in[6];
    const float* ln1_g    = (const float*)d_in[7];
    const float* ln1_b    = (const float*)d_in[8];
    const float* Wq       = (const float*)d_in[9];
    const float* bq       = (const float*)d_in[10];
    const float* Wk       = (const float*)d_in[11];
    const float* bk       = (const float*)d_in[12];
    const float* Wv       = (const float*)d_in[13];
    const float* bv       = (const float*)d_in[14];
    const float* Wo       = (const float*)d_in[15];
    const float* bo       = (const float*)d_in[16];
    const float* ln2_g    = (const float*)d_in[17];
    const float* ln2_b    = (const float*)d_in[18];
    const float* W1       = (const float*)d_in[19];
    const float* b1       = (const float*)d_in[20];
    const float* W2       = (const float*)d_in[21];
    const float* b2       = (const float*)d_in[22];
    const float* Wc1      = (const float*)d_in[23];
    const float* bc1      = (const float*)d_in[24];
    const float* lnc_g    = (const float*)d_in[25];
    const float* lnc_b    = (const float*)d_in[26];
    const float* Wc2      = (const float*)d_in[27];
    const float* bc2      = (const float*)d_in[28];

    float *h, *y, *q, *k, *v, *mlp, *pp;
    cudaGetSymbolAddress((void**)&h,   g_h);
    cudaGetSymbolAddress((void**)&y,   g_y);
    cudaGetSymbolAddress((void**)&q,   g_q);
    cudaGetSymbolAddress((void**)&k,   g_k);
    cudaGetSymbolAddress((void**)&v,   g_v);
    cudaGetSymbolAddress((void**)&mlp, g_m);
    cudaGetSymbolAddress((void**)&pp,  g_pp);

    embed_kernel<<<Bq * Nn, 256>>>(x, W_emb, b_emb, g_emb, be_emb, h);
    cls_kernel<<<Bq, 256>>>(cls_tok, h);

    const int M = Mrows;                               // 8200
    dim3 gemm256(Ee / GBN, (M + GBM - 1) / GBM);       // (4, 65)
    dim3 gemm1024(XE / GBN, (M + GBM - 1) / GBM);      // (16, 65)
    dim3 fgrid((Tt + 31) / 32, Bq * Hh);               // (33, 64)

    for (int l = 0; l < Ll; ++l) {
        addpos_ln_kernel<<<M, 256>>>(h, pos, ln1_g + l * Ee, ln1_b + l * Ee, y);

        gemm2_kernel<EPI_NONE><<<gemm256, 256>>>(y, Wq + (size_t)l * Ee * Ee, bq + l * Ee, nullptr, q, M, Ee, Ee);
        gemm2_kernel<EPI_NONE><<<gemm256, 256>>>(y, Wk + (size_t)l * Ee * Ee, bk + l * Ee, nullptr, k, M, Ee, Ee);
        gemm2_kernel<EPI_NONE><<<gemm256, 256>>>(y, Wv + (size_t)l * Ee * Ee, bv + l * Ee, nullptr, v, M, Ee, Ee);

        flash_attn_kernel<<<fgrid, 256>>>(q, k, v, y);  // y reused as attn output

        gemm2_kernel<EPI_ADD><<<gemm256, 256>>>(y, Wo + (size_t)l * Ee * Ee, bo + l * Ee, h, h, M, Ee, Ee);

        ln_kernel<<<M, 256>>>(h, ln2_g + l * Ee, ln2_b + l * Ee, y);
        gemm2_kernel<EPI_GELU><<<gemm1024, 256>>>(y, W1 + (size_t)l * Ee * XE, b1 + l * XE, nullptr, mlp, M, XE, Ee);
        gemm2_kernel<EPI_ADD><<<gemm256, 256>>>(mlp, W2 + (size_t)l * XE * Ee, b2 + l * Ee, h, h, M, Ee, XE);
    }

    dim3 pgrid(4, Bq);
    pool_partial_kernel<<<pgrid, 256>>>(h, pp);
    classifier_kernel<<<Bq, 256>>>(pp, Wc1, bc1, lnc_g, lnc_b, Wc2, bc2, (float*)d_out);
}